// round 6
// baseline (speedup 1.0000x reference)
#include <cuda_runtime.h>
#include <cstdint>

#define TT 100
#define DD 32
#define AA 16
#define NPAIR 4950
#define NTASK 160
#define NPP (NTASK*32)      // 5120, padded pair space
#define TTP 101             // odd pad for esT2 rows
#define NTHREADS 128
#define NW (NTHREADS/32)
#define BSZ 1024

typedef unsigned long long ull;

// pair index table: (i<<8)|j for itertools.combinations order; dummies = (0,1)
__device__ __align__(16) int g_pairIJ[NPP];

// small weights in constant memory (constant port, not L1tex)
__constant__ __align__(16) ulonglong2 cW2[DD*4];   // W row-major: row k = 16 floats = 4 ulonglong2
__constant__ float cb[AA];
__constant__ float ch[AA];
__constant__ float cW1[DD*16];
__constant__ float cb1[16];
__constant__ float cW2m[16*8];
__constant__ float cb2[8];
__constant__ float cWf[8];
__constant__ float cbf[1];

__global__ void setup_pairs_kernel() {
    int p = blockIdx.x * blockDim.x + threadIdx.x;
    if (p >= NPP) return;
    if (p >= NPAIR) { g_pairIJ[p] = 1; return; }   // dummy pair (0,1)
    float disc = (float)((2*TT-1)*(2*TT-1) - 8*p);
    int i = (int)(((float)(2*TT-1) - sqrtf(disc)) * 0.5f);
    if (i < 0) i = 0;
    if (i > TT-2) i = TT-2;
    while (i > 0    && (i*(2*TT-1-i))/2 > p) i--;
    while (i < TT-2 && ((i+1)*(2*TT-1-(i+1)))/2 <= p) i++;
    int off = (i*(2*TT-1-i))/2;
    int j = p - off + i + 1;
    g_pairIJ[p] = (i << 8) | j;
}

__global__ __launch_bounds__(NTHREADS, 5) void afm_kernel(
    const int*   __restrict__ x,
    const float* __restrict__ Emb,
    float* __restrict__ out)
{
    __shared__ __align__(16) float2 esT2[AA][TTP];  // [k2][t]: dims (2k2, 2k2+1)
    __shared__ __align__(16) float att[NPP];        // exp(logit), 0 on dummies
    __shared__ int   xs[TT];
    __shared__ float red[NW];
    __shared__ float poolv[DD];
    __shared__ float o1s[16];
    __shared__ float o2s[8];
    __shared__ float sm_isum;

    const int tid  = threadIdx.x;
    const int bidx = blockIdx.x;
    const int lane = tid & 31;
    const int wid  = tid >> 5;

    // ---- stage x indices, gather embeddings transposed: esT2[d2][t] ----
    if (tid < TT) xs[tid] = x[bidx*TT + tid];
    __syncthreads();
    for (int idx = tid; idx < TT*AA; idx += NTHREADS) {
        int t = idx >> 4, d2 = idx & 15;
        float2 v = ((const float2*)Emb)[(size_t)xs[t] * AA + d2];
        esT2[d2][t] = v;
    }
    __syncthreads();

    // ================= PASS 1: exp(logit) per pair =================
    // warp-chunk = 32 consecutive pairs (lane = pair): i ~broadcast, j consecutive
    // (no max-subtraction: logits are O(0.01); softmax ratio identical)
    float lsum = 0.f;
    for (int t0 = wid*2; t0 < NTASK; t0 += NW*2) {
        const int pA = t0*32 + lane;
        const int pB = pA + 32;
        int vA = g_pairIJ[pA], vB = g_pairIJ[pB];
        int iA = vA >> 8, jA = vA & 255;
        int iB = vB >> 8, jB = vB & 255;

        ull zzA[AA/2], zzB[AA/2];
        #pragma unroll
        for (int q = 0; q < AA/2; q++) { zzA[q] = 0ull; zzB[q] = 0ull; }

        #pragma unroll
        for (int k2 = 0; k2 < AA; k2++) {
            // conflict-free LDS.64: i broadcast-ish, j lane-consecutive
            float2 eiA = esT2[k2][iA], ejA = esT2[k2][jA];
            float2 eiB = esT2[k2][iB], ejB = esT2[k2][jB];
            #pragma unroll
            for (int kk = 0; kk < 2; kk++) {
                // W row (2*k2+kk): 16 floats via 4 LDC.128, amortized over 64 pairs
                ull w2[AA/2];
                #pragma unroll
                for (int q2 = 0; q2 < 4; q2++) {
                    ulonglong2 t2 = cW2[(2*k2+kk)*4 + q2];
                    w2[2*q2] = t2.x; w2[2*q2+1] = t2.y;
                }
                float pmA = kk ? (eiA.y * ejA.y) : (eiA.x * ejA.x);
                float pmB = kk ? (eiB.y * ejB.y) : (eiB.x * ejB.x);
                ull ppA, ppB;
                asm("mov.b64 %0, {%1, %1};" : "=l"(ppA) : "f"(pmA));
                asm("mov.b64 %0, {%1, %1};" : "=l"(ppB) : "f"(pmB));
                #pragma unroll
                for (int q = 0; q < AA/2; q++) {
                    asm("fma.rn.f32x2 %0, %1, %2, %0;" : "+l"(zzA[q]) : "l"(ppA), "l"(w2[q]));
                    asm("fma.rn.f32x2 %0, %1, %2, %0;" : "+l"(zzB[q]) : "l"(ppB), "l"(w2[q]));
                }
            }
        }
        // bias + relu + dot(h) + exp epilogue; coalesced att store
        float logitA = 0.f, logitB = 0.f;
        #pragma unroll
        for (int q = 0; q < AA/2; q++) {
            float loA, hiA, loB, hiB;
            asm("mov.b64 {%0, %1}, %2;" : "=f"(loA), "=f"(hiA) : "l"(zzA[q]));
            asm("mov.b64 {%0, %1}, %2;" : "=f"(loB), "=f"(hiB) : "l"(zzB[q]));
            logitA = fmaf(fmaxf(loA + cb[2*q],   0.f), ch[2*q],   logitA);
            logitA = fmaf(fmaxf(hiA + cb[2*q+1], 0.f), ch[2*q+1], logitA);
            logitB = fmaf(fmaxf(loB + cb[2*q],   0.f), ch[2*q],   logitB);
            logitB = fmaf(fmaxf(hiB + cb[2*q+1], 0.f), ch[2*q+1], logitB);
        }
        float EA = (pA < NPAIR) ? __expf(logitA) : 0.f;
        float EB = (pB < NPAIR) ? __expf(logitB) : 0.f;
        att[pA] = EA;
        att[pB] = EB;
        lsum += EA + EB;
    }

    // ---- block reduce lsum -> 1/sum ----
    #pragma unroll
    for (int o = 16; o > 0; o >>= 1) lsum += __shfl_xor_sync(0xffffffffu, lsum, o);
    if (lane == 0) red[wid] = lsum;
    __syncthreads();
    if (tid == 0) {
        float s = 0.f;
        #pragma unroll
        for (int w = 0; w < NW; w++) s += red[w];
        sm_isum = 1.f / s;
    }
    __syncthreads();
    const float inv = sm_isum;

    // ================= PASS 2: attention-pooled sum (transposed layout) ======
    // warp owns 4 float2-dims (d2 = wid*4+q); lanes stream 32 consecutive pairs
    {
        ull acc[4];
        #pragma unroll
        for (int q = 0; q < 4; q++) acc[q] = 0ull;
        const int d2base = wid * 4;

        for (int p0 = 0; p0 < NPP; p0 += 32) {
            int v = g_pairIJ[p0 + lane];
            float a = att[p0 + lane];          // coalesced LDS; 0 on dummies
            int i = v >> 8, j = v & 255;
            ull aa;
            asm("mov.b64 %0, {%1, %1};" : "=l"(aa) : "f"(a));
            #pragma unroll
            for (int q = 0; q < 4; q++) {
                ull vi = *(const ull*)&esT2[d2base + q][i];  // broadcast-ish
                ull vj = *(const ull*)&esT2[d2base + q][j];  // consecutive
                ull prod;
                asm("mul.rn.f32x2 %0, %1, %2;" : "=l"(prod) : "l"(vi), "l"(vj));
                asm("fma.rn.f32x2 %0, %1, %2, %0;" : "+l"(acc[q]) : "l"(aa), "l"(prod));
            }
        }
        // warp-reduce 8 floats, lane 0 writes poolv (already scaled by inv)
        #pragma unroll
        for (int q = 0; q < 4; q++) {
            float lo, hi;
            asm("mov.b64 {%0, %1}, %2;" : "=f"(lo), "=f"(hi) : "l"(acc[q]));
            #pragma unroll
            for (int o = 16; o > 0; o >>= 1) {
                lo += __shfl_xor_sync(0xffffffffu, lo, o);
                hi += __shfl_xor_sync(0xffffffffu, hi, o);
            }
            if (lane == 0) {
                poolv[2*(d2base+q)]   = lo * inv;
                poolv[2*(d2base+q)+1] = hi * inv;
            }
        }
    }
    __syncthreads();

    // ================= tiny MLP (weights from constant) =================
    if (tid < 16) {
        float z = cb1[tid];
        #pragma unroll
        for (int d = 0; d < DD; d++) z = fmaf(poolv[d], cW1[d*16 + tid], z);
        o1s[tid] = fmaxf(z, 0.f);
    }
    __syncthreads();
    if (tid < 8) {
        float z = cb2[tid];
        #pragma unroll
        for (int c = 0; c < 16; c++) z = fmaf(o1s[c], cW2m[c*8 + tid], z);
        o2s[tid] = fmaxf(z, 0.f);
    }
    __syncthreads();
    if (tid == 0) {
        float z = cbf[0];
        #pragma unroll
        for (int c = 0; c < 8; c++) z = fmaf(o2s[c], cWf[c], z);
        out[bidx] = 1.f / (1.f + __expf(-z));
    }
}

extern "C" void kernel_launch(void* const* d_in, const int* in_sizes, int n_in,
                              void* d_out, int out_size) {
    const int*   x   = (const int*)  d_in[0];
    const float* Emb = (const float*)d_in[1];
    float* out = (float*)d_out;

    // stage small weights into constant memory (async D2D: graph-capturable)
    cudaMemcpyToSymbolAsync(cW2,  d_in[2],  DD*AA*sizeof(float), 0, cudaMemcpyDeviceToDevice);
    cudaMemcpyToSymbolAsync(cb,   d_in[3],  AA*sizeof(float),    0, cudaMemcpyDeviceToDevice);
    cudaMemcpyToSymbolAsync(ch,   d_in[4],  AA*sizeof(float),    0, cudaMemcpyDeviceToDevice);
    cudaMemcpyToSymbolAsync(cW1,  d_in[5],  DD*16*sizeof(float), 0, cudaMemcpyDeviceToDevice);
    cudaMemcpyToSymbolAsync(cb1,  d_in[6],  16*sizeof(float),    0, cudaMemcpyDeviceToDevice);
    cudaMemcpyToSymbolAsync(cW2m, d_in[7],  16*8*sizeof(float),  0, cudaMemcpyDeviceToDevice);
    cudaMemcpyToSymbolAsync(cb2,  d_in[8],  8*sizeof(float),     0, cudaMemcpyDeviceToDevice);
    cudaMemcpyToSymbolAsync(cWf,  d_in[9],  8*sizeof(float),     0, cudaMemcpyDeviceToDevice);
    cudaMemcpyToSymbolAsync(cbf,  d_in[10], 1*sizeof(float),     0, cudaMemcpyDeviceToDevice);

    setup_pairs_kernel<<<(NPP + 255)/256, 256>>>();
    afm_kernel<<<BSZ, NTHREADS>>>(x, Emb, out);
}

// round 7
// speedup vs baseline: 1.0053x; 1.0053x over previous
#include <cuda_runtime.h>
#include <cstdint>

#define TT 100
#define DD 32
#define AA 16
#define NPAIR 4950
#define NTASK 160
#define NPP (NTASK*32)      // 5120, padded pair space
#define TTP 101             // odd pad for esT2 rows
#define NTHREADS 128
#define NW (NTHREADS/32)
#define BSZ 1024

typedef unsigned long long ull;

// pair index table: (i<<8)|j for itertools.combinations order; dummies = (0,1)
__device__ __align__(16) int g_pairIJ[NPP];

// small weights in constant memory (constant port, not L1tex)
__constant__ __align__(16) ulonglong2 cW2[DD*4];   // W row-major: row k = 16 floats = 4 ulonglong2
__constant__ float cb[AA];
__constant__ float ch[AA];
__constant__ float cW1[DD*16];
__constant__ float cb1[16];
__constant__ float cW2m[16*8];
__constant__ float cb2[8];
__constant__ float cWf[8];
__constant__ float cbf[1];

__global__ void setup_pairs_kernel() {
    int p = blockIdx.x * blockDim.x + threadIdx.x;
    if (p >= NPP) return;
    if (p >= NPAIR) { g_pairIJ[p] = 1; return; }   // dummy pair (0,1)
    float disc = (float)((2*TT-1)*(2*TT-1) - 8*p);
    int i = (int)(((float)(2*TT-1) - sqrtf(disc)) * 0.5f);
    if (i < 0) i = 0;
    if (i > TT-2) i = TT-2;
    while (i > 0    && (i*(2*TT-1-i))/2 > p) i--;
    while (i < TT-2 && ((i+1)*(2*TT-1-(i+1)))/2 <= p) i++;
    int off = (i*(2*TT-1-i))/2;
    int j = p - off + i + 1;
    g_pairIJ[p] = (i << 8) | j;
}

__global__ __launch_bounds__(NTHREADS, 5) void afm_kernel(
    const int*   __restrict__ x,
    const float* __restrict__ Emb,
    float* __restrict__ out)
{
    __shared__ __align__(16) float2 esT2[AA][TTP];  // [k2][t]: dims (2k2, 2k2+1)
    __shared__ __align__(16) float att[NPP];        // exp(logit), 0 on dummies
    __shared__ int   xs[TT];
    __shared__ float red[NW];
    __shared__ float poolv[DD];
    __shared__ float o1s[16];
    __shared__ float o2s[8];
    __shared__ float sm_isum;

    const int tid  = threadIdx.x;
    const int bidx = blockIdx.x;
    const int lane = tid & 31;
    const int wid  = tid >> 5;

    // ---- stage x indices, gather embeddings transposed: esT2[d2][t] ----
    if (tid < TT) xs[tid] = x[bidx*TT + tid];
    __syncthreads();
    for (int idx = tid; idx < TT*AA; idx += NTHREADS) {
        int t = idx >> 4, d2 = idx & 15;
        float2 v = ((const float2*)Emb)[(size_t)xs[t] * AA + d2];
        esT2[d2][t] = v;
    }
    __syncthreads();

    // ================= PASS 1: exp(logit) per pair =================
    // warp-chunk = 32 consecutive pairs (lane = pair): i ~broadcast, j consecutive
    // (no max-subtraction: logits are O(0.01); softmax ratio identical)
    float lsum = 0.f;
    for (int t0 = wid*2; t0 < NTASK; t0 += NW*2) {
        const int pA = t0*32 + lane;
        const int pB = pA + 32;
        int vA = g_pairIJ[pA], vB = g_pairIJ[pB];
        int iA = vA >> 8, jA = vA & 255;
        int iB = vB >> 8, jB = vB & 255;

        ull zzA[AA/2], zzB[AA/2];
        #pragma unroll
        for (int q = 0; q < AA/2; q++) { zzA[q] = 0ull; zzB[q] = 0ull; }

        #pragma unroll
        for (int k2 = 0; k2 < AA; k2++) {
            // conflict-free LDS.64: i broadcast-ish, j lane-consecutive
            float2 eiA = esT2[k2][iA], ejA = esT2[k2][jA];
            float2 eiB = esT2[k2][iB], ejB = esT2[k2][jB];
            #pragma unroll
            for (int kk = 0; kk < 2; kk++) {
                // W row (2*k2+kk): 16 floats via 4 LDC.128, amortized over 64 pairs
                ull w2[AA/2];
                #pragma unroll
                for (int q2 = 0; q2 < 4; q2++) {
                    ulonglong2 t2 = cW2[(2*k2+kk)*4 + q2];
                    w2[2*q2] = t2.x; w2[2*q2+1] = t2.y;
                }
                float pmA = kk ? (eiA.y * ejA.y) : (eiA.x * ejA.x);
                float pmB = kk ? (eiB.y * ejB.y) : (eiB.x * ejB.x);
                ull ppA, ppB;
                asm("mov.b64 %0, {%1, %1};" : "=l"(ppA) : "f"(pmA));
                asm("mov.b64 %0, {%1, %1};" : "=l"(ppB) : "f"(pmB));
                #pragma unroll
                for (int q = 0; q < AA/2; q++) {
                    asm("fma.rn.f32x2 %0, %1, %2, %0;" : "+l"(zzA[q]) : "l"(ppA), "l"(w2[q]));
                    asm("fma.rn.f32x2 %0, %1, %2, %0;" : "+l"(zzB[q]) : "l"(ppB), "l"(w2[q]));
                }
            }
        }
        // bias + relu + dot(h) + exp epilogue; coalesced att store
        float logitA = 0.f, logitB = 0.f;
        #pragma unroll
        for (int q = 0; q < AA/2; q++) {
            float loA, hiA, loB, hiB;
            asm("mov.b64 {%0, %1}, %2;" : "=f"(loA), "=f"(hiA) : "l"(zzA[q]));
            asm("mov.b64 {%0, %1}, %2;" : "=f"(loB), "=f"(hiB) : "l"(zzB[q]));
            logitA = fmaf(fmaxf(loA + cb[2*q],   0.f), ch[2*q],   logitA);
            logitA = fmaf(fmaxf(hiA + cb[2*q+1], 0.f), ch[2*q+1], logitA);
            logitB = fmaf(fmaxf(loB + cb[2*q],   0.f), ch[2*q],   logitB);
            logitB = fmaf(fmaxf(hiB + cb[2*q+1], 0.f), ch[2*q+1], logitB);
        }
        float EA = (pA < NPAIR) ? __expf(logitA) : 0.f;
        float EB = (pB < NPAIR) ? __expf(logitB) : 0.f;
        att[pA] = EA;
        att[pB] = EB;
        lsum += EA + EB;
    }

    // ---- block reduce lsum -> 1/sum ----
    #pragma unroll
    for (int o = 16; o > 0; o >>= 1) lsum += __shfl_xor_sync(0xffffffffu, lsum, o);
    if (lane == 0) red[wid] = lsum;
    __syncthreads();
    if (tid == 0) {
        float s = 0.f;
        #pragma unroll
        for (int w = 0; w < NW; w++) s += red[w];
        sm_isum = 1.f / s;
    }
    __syncthreads();
    const float inv = sm_isum;

    // ================= PASS 2: attention-pooled sum (transposed layout) ======
    // warp owns 4 float2-dims (d2 = wid*4+q); lanes stream 32 consecutive pairs
    {
        ull acc[4];
        #pragma unroll
        for (int q = 0; q < 4; q++) acc[q] = 0ull;
        const int d2base = wid * 4;

        for (int p0 = 0; p0 < NPP; p0 += 32) {
            int v = g_pairIJ[p0 + lane];
            float a = att[p0 + lane];          // coalesced LDS; 0 on dummies
            int i = v >> 8, j = v & 255;
            ull aa;
            asm("mov.b64 %0, {%1, %1};" : "=l"(aa) : "f"(a));
            #pragma unroll
            for (int q = 0; q < 4; q++) {
                ull vi = *(const ull*)&esT2[d2base + q][i];  // broadcast-ish
                ull vj = *(const ull*)&esT2[d2base + q][j];  // consecutive
                ull prod;
                asm("mul.rn.f32x2 %0, %1, %2;" : "=l"(prod) : "l"(vi), "l"(vj));
                asm("fma.rn.f32x2 %0, %1, %2, %0;" : "+l"(acc[q]) : "l"(aa), "l"(prod));
            }
        }
        // warp-reduce 8 floats, lane 0 writes poolv (already scaled by inv)
        #pragma unroll
        for (int q = 0; q < 4; q++) {
            float lo, hi;
            asm("mov.b64 {%0, %1}, %2;" : "=f"(lo), "=f"(hi) : "l"(acc[q]));
            #pragma unroll
            for (int o = 16; o > 0; o >>= 1) {
                lo += __shfl_xor_sync(0xffffffffu, lo, o);
                hi += __shfl_xor_sync(0xffffffffu, hi, o);
            }
            if (lane == 0) {
                poolv[2*(d2base+q)]   = lo * inv;
                poolv[2*(d2base+q)+1] = hi * inv;
            }
        }
    }
    __syncthreads();

    // ================= tiny MLP (weights from constant) =================
    if (tid < 16) {
        float z = cb1[tid];
        #pragma unroll
        for (int d = 0; d < DD; d++) z = fmaf(poolv[d], cW1[d*16 + tid], z);
        o1s[tid] = fmaxf(z, 0.f);
    }
    __syncthreads();
    if (tid < 8) {
        float z = cb2[tid];
        #pragma unroll
        for (int c = 0; c < 16; c++) z = fmaf(o1s[c], cW2m[c*8 + tid], z);
        o2s[tid] = fmaxf(z, 0.f);
    }
    __syncthreads();
    if (tid == 0) {
        float z = cbf[0];
        #pragma unroll
        for (int c = 0; c < 8; c++) z = fmaf(o2s[c], cWf[c], z);
        out[bidx] = 1.f / (1.f + __expf(-z));
    }
}

extern "C" void kernel_launch(void* const* d_in, const int* in_sizes, int n_in,
                              void* d_out, int out_size) {
    const int*   x   = (const int*)  d_in[0];
    const float* Emb = (const float*)d_in[1];
    float* out = (float*)d_out;

    // stage small weights into constant memory (async D2D: graph-capturable)
    cudaMemcpyToSymbolAsync(cW2,  d_in[2],  DD*AA*sizeof(float), 0, cudaMemcpyDeviceToDevice);
    cudaMemcpyToSymbolAsync(cb,   d_in[3],  AA*sizeof(float),    0, cudaMemcpyDeviceToDevice);
    cudaMemcpyToSymbolAsync(ch,   d_in[4],  AA*sizeof(float),    0, cudaMemcpyDeviceToDevice);
    cudaMemcpyToSymbolAsync(cW1,  d_in[5],  DD*16*sizeof(float), 0, cudaMemcpyDeviceToDevice);
    cudaMemcpyToSymbolAsync(cb1,  d_in[6],  16*sizeof(float),    0, cudaMemcpyDeviceToDevice);
    cudaMemcpyToSymbolAsync(cW2m, d_in[7],  16*8*sizeof(float),  0, cudaMemcpyDeviceToDevice);
    cudaMemcpyToSymbolAsync(cb2,  d_in[8],  8*sizeof(float),     0, cudaMemcpyDeviceToDevice);
    cudaMemcpyToSymbolAsync(cWf,  d_in[9],  8*sizeof(float),     0, cudaMemcpyDeviceToDevice);
    cudaMemcpyToSymbolAsync(cbf,  d_in[10], 1*sizeof(float),     0, cudaMemcpyDeviceToDevice);

    setup_pairs_kernel<<<(NPP + 255)/256, 256>>>();
    afm_kernel<<<BSZ, NTHREADS>>>(x, Emb, out);
}

// round 8
// speedup vs baseline: 1.0333x; 1.0279x over previous
#include <cuda_runtime.h>
#include <cstdint>

#define TT 100
#define DD 32
#define AA 16
#define NPAIR 4950
#define NTASK 156
#define NPP (NTASK*32)      // 4992, padded pair space
#define TTP 100             // no pad needed: j-consecutive & broadcast patterns
#define NTHREADS 128
#define NW (NTHREADS/32)
#define BSZ 1024

typedef unsigned long long ull;

// pair index table: (i<<8)|j for itertools.combinations order; dummies = (0,1)
__device__ __align__(16) int g_pairIJ[NPP];

// small weights in constant memory (constant port, not L1tex)
__constant__ __align__(16) ulonglong2 cW2[DD*4];   // W row-major: row k = 16 floats = 4 ulonglong2
__constant__ __align__(16) float cb[AA];
__constant__ __align__(16) float ch[AA];
__constant__ float cW1[DD*16];
__constant__ float cb1[16];
__constant__ float cW2m[16*8];
__constant__ float cb2[8];
__constant__ float cWf[8];
__constant__ float cbf[1];

__global__ void setup_pairs_kernel() {
    int p = blockIdx.x * blockDim.x + threadIdx.x;
    if (p >= NPP) return;
    if (p >= NPAIR) { g_pairIJ[p] = 1; return; }   // dummy pair (0,1)
    float disc = (float)((2*TT-1)*(2*TT-1) - 8*p);
    int i = (int)(((float)(2*TT-1) - sqrtf(disc)) * 0.5f);
    if (i < 0) i = 0;
    if (i > TT-2) i = TT-2;
    while (i > 0    && (i*(2*TT-1-i))/2 > p) i--;
    while (i < TT-2 && ((i+1)*(2*TT-1-(i+1)))/2 <= p) i++;
    int off = (i*(2*TT-1-i))/2;
    int j = p - off + i + 1;
    g_pairIJ[p] = (i << 8) | j;
}

__global__ __launch_bounds__(NTHREADS, 6) void afm_kernel(
    const int*   __restrict__ x,
    const float* __restrict__ Emb,
    float* __restrict__ out)
{
    __shared__ __align__(16) float2 esT2[AA][TTP];  // [k2][t]: dims (2k2, 2k2+1)
    __shared__ __align__(16) float att[NPP];        // exp(logit), 0 on dummies
    __shared__ int   xs[TT];
    __shared__ float red[NW];
    __shared__ float poolv[DD];
    __shared__ float o1s[16];
    __shared__ float o2s[8];
    __shared__ float sm_isum;

    const int tid  = threadIdx.x;
    const int bidx = blockIdx.x;
    const int lane = tid & 31;
    const int wid  = tid >> 5;

    // ---- stage x indices, gather embeddings transposed: esT2[d2][t] ----
    if (tid < TT) xs[tid] = x[bidx*TT + tid];
    __syncthreads();
    for (int idx = tid; idx < TT*AA; idx += NTHREADS) {
        int t = idx >> 4, d2 = idx & 15;
        float2 v = ((const float2*)Emb)[(size_t)xs[t] * AA + d2];
        esT2[d2][t] = v;
    }
    __syncthreads();

    // ================= PASS 1: exp(logit) per pair =================
    // warp-chunk = 32 consecutive pairs (lane = pair): i ~broadcast, j consecutive
    // (no max-subtraction: logits are O(0.01); softmax ratio identical)
    float lsum = 0.f;
    for (int t0 = wid*2; t0 < NTASK; t0 += NW*2) {
        const int pA = t0*32 + lane;
        const int pB = pA + 32;                    // t0+1 < NTASK by construction
        int vA = g_pairIJ[pA], vB = g_pairIJ[pB];
        int iA = vA >> 8, jA = vA & 255;
        int iB = vB >> 8, jB = vB & 255;

        // accumulators packed over A; bias folded into init (LDC.64, const port)
        ull zzA[AA/2], zzB[AA/2];
        #pragma unroll
        for (int q = 0; q < AA/2; q++) {
            ull bq = *(const ull*)&cb[2*q];
            zzA[q] = bq; zzB[q] = bq;
        }

        #pragma unroll
        for (int k2 = 0; k2 < AA; k2++) {
            // conflict-free LDS.64: i broadcast-ish, j lane-consecutive
            ull eiA = *(const ull*)&esT2[k2][iA];
            ull ejA = *(const ull*)&esT2[k2][jA];
            ull eiB = *(const ull*)&esT2[k2][iB];
            ull ejB = *(const ull*)&esT2[k2][jB];

            // both k-parity products in ONE fma-pipe slot per pair
            ull prodA, prodB;
            asm("mul.rn.f32x2 %0, %1, %2;" : "=l"(prodA) : "l"(eiA), "l"(ejA));
            asm("mul.rn.f32x2 %0, %1, %2;" : "=l"(prodB) : "l"(eiB), "l"(ejB));
            float pA0, pA1, pB0, pB1;
            asm("mov.b64 {%0,%1}, %2;" : "=f"(pA0), "=f"(pA1) : "l"(prodA));
            asm("mov.b64 {%0,%1}, %2;" : "=f"(pB0), "=f"(pB1) : "l"(prodB));
            ull ppA0, ppA1, ppB0, ppB1;
            asm("mov.b64 %0, {%1,%1};" : "=l"(ppA0) : "f"(pA0));
            asm("mov.b64 %0, {%1,%1};" : "=l"(ppA1) : "f"(pA1));
            asm("mov.b64 %0, {%1,%1};" : "=l"(ppB0) : "f"(pB0));
            asm("mov.b64 %0, {%1,%1};" : "=l"(ppB1) : "f"(pB1));

            #pragma unroll
            for (int kk = 0; kk < 2; kk++) {
                // W row (2*k2+kk): 16 floats via 4 LDC.128, amortized over 64 pairs
                ull w2[AA/2];
                #pragma unroll
                for (int q2 = 0; q2 < 4; q2++) {
                    ulonglong2 t2 = cW2[(2*k2+kk)*4 + q2];
                    w2[2*q2] = t2.x; w2[2*q2+1] = t2.y;
                }
                ull ppA = kk ? ppA1 : ppA0;
                ull ppB = kk ? ppB1 : ppB0;
                #pragma unroll
                for (int q = 0; q < AA/2; q++) {
                    asm("fma.rn.f32x2 %0, %1, %2, %0;" : "+l"(zzA[q]) : "l"(ppA), "l"(w2[q]));
                    asm("fma.rn.f32x2 %0, %1, %2, %0;" : "+l"(zzB[q]) : "l"(ppB), "l"(w2[q]));
                }
            }
        }
        // relu + dot(h) + exp epilogue (bias already in accumulators)
        float lA0 = 0.f, lA1 = 0.f, lB0 = 0.f, lB1 = 0.f;
        #pragma unroll
        for (int q = 0; q < AA/2; q++) {
            float loA, hiA, loB, hiB;
            asm("mov.b64 {%0, %1}, %2;" : "=f"(loA), "=f"(hiA) : "l"(zzA[q]));
            asm("mov.b64 {%0, %1}, %2;" : "=f"(loB), "=f"(hiB) : "l"(zzB[q]));
            lA0 = fmaf(fmaxf(loA, 0.f), ch[2*q],   lA0);
            lA1 = fmaf(fmaxf(hiA, 0.f), ch[2*q+1], lA1);
            lB0 = fmaf(fmaxf(loB, 0.f), ch[2*q],   lB0);
            lB1 = fmaf(fmaxf(hiB, 0.f), ch[2*q+1], lB1);
        }
        float EA = (pA < NPAIR) ? __expf(lA0 + lA1) : 0.f;
        float EB = (pB < NPAIR) ? __expf(lB0 + lB1) : 0.f;
        att[pA] = EA;
        att[pB] = EB;
        lsum += EA + EB;
    }

    // ---- block reduce lsum -> 1/sum ----
    #pragma unroll
    for (int o = 16; o > 0; o >>= 1) lsum += __shfl_xor_sync(0xffffffffu, lsum, o);
    if (lane == 0) red[wid] = lsum;
    __syncthreads();
    if (tid == 0) {
        float s = 0.f;
        #pragma unroll
        for (int w = 0; w < NW; w++) s += red[w];
        sm_isum = 1.f / s;
    }
    __syncthreads();
    const float inv = sm_isum;

    // ================= PASS 2: attention-pooled sum (transposed layout) ======
    // warp owns 4 float2-dims (d2 = wid*4+q); lanes stream 32 consecutive pairs
    {
        ull acc[4];
        #pragma unroll
        for (int q = 0; q < 4; q++) acc[q] = 0ull;
        const int d2base = wid * 4;

        for (int p0 = 0; p0 < NPP; p0 += 32) {
            int v = g_pairIJ[p0 + lane];
            float a = att[p0 + lane];          // coalesced LDS; 0 on dummies
            int i = v >> 8, j = v & 255;
            ull aa;
            asm("mov.b64 %0, {%1, %1};" : "=l"(aa) : "f"(a));
            #pragma unroll
            for (int q = 0; q < 4; q++) {
                ull vi = *(const ull*)&esT2[d2base + q][i];  // broadcast-ish
                ull vj = *(const ull*)&esT2[d2base + q][j];  // consecutive
                ull prod;
                asm("mul.rn.f32x2 %0, %1, %2;" : "=l"(prod) : "l"(vi), "l"(vj));
                asm("fma.rn.f32x2 %0, %1, %2, %0;" : "+l"(acc[q]) : "l"(aa), "l"(prod));
            }
        }
        // warp-reduce 8 floats, lane 0 writes poolv (already scaled by inv)
        #pragma unroll
        for (int q = 0; q < 4; q++) {
            float lo, hi;
            asm("mov.b64 {%0, %1}, %2;" : "=f"(lo), "=f"(hi) : "l"(acc[q]));
            #pragma unroll
            for (int o = 16; o > 0; o >>= 1) {
                lo += __shfl_xor_sync(0xffffffffu, lo, o);
                hi += __shfl_xor_sync(0xffffffffu, hi, o);
            }
            if (lane == 0) {
                poolv[2*(d2base+q)]   = lo * inv;
                poolv[2*(d2base+q)+1] = hi * inv;
            }
        }
    }
    __syncthreads();

    // ================= tiny MLP (weights from constant) =================
    if (tid < 16) {
        float z = cb1[tid];
        #pragma unroll
        for (int d = 0; d < DD; d++) z = fmaf(poolv[d], cW1[d*16 + tid], z);
        o1s[tid] = fmaxf(z, 0.f);
    }
    __syncthreads();
    if (tid < 8) {
        float z = cb2[tid];
        #pragma unroll
        for (int c = 0; c < 16; c++) z = fmaf(o1s[c], cW2m[c*8 + tid], z);
        o2s[tid] = fmaxf(z, 0.f);
    }
    __syncthreads();
    if (tid == 0) {
        float z = cbf[0];
        #pragma unroll
        for (int c = 0; c < 8; c++) z = fmaf(o2s[c], cWf[c], z);
        out[bidx] = 1.f / (1.f + __expf(-z));
    }
}

extern "C" void kernel_launch(void* const* d_in, const int* in_sizes, int n_in,
                              void* d_out, int out_size) {
    const int*   x   = (const int*)  d_in[0];
    const float* Emb = (const float*)d_in[1];
    float* out = (float*)d_out;

    // stage small weights into constant memory (async D2D: graph-capturable)
    cudaMemcpyToSymbolAsync(cW2,  d_in[2],  DD*AA*sizeof(float), 0, cudaMemcpyDeviceToDevice);
    cudaMemcpyToSymbolAsync(cb,   d_in[3],  AA*sizeof(float),    0, cudaMemcpyDeviceToDevice);
    cudaMemcpyToSymbolAsync(ch,   d_in[4],  AA*sizeof(float),    0, cudaMemcpyDeviceToDevice);
    cudaMemcpyToSymbolAsync(cW1,  d_in[5],  DD*16*sizeof(float), 0, cudaMemcpyDeviceToDevice);
    cudaMemcpyToSymbolAsync(cb1,  d_in[6],  16*sizeof(float),    0, cudaMemcpyDeviceToDevice);
    cudaMemcpyToSymbolAsync(cW2m, d_in[7],  16*8*sizeof(float),  0, cudaMemcpyDeviceToDevice);
    cudaMemcpyToSymbolAsync(cb2,  d_in[8],  8*sizeof(float),     0, cudaMemcpyDeviceToDevice);
    cudaMemcpyToSymbolAsync(cWf,  d_in[9],  8*sizeof(float),     0, cudaMemcpyDeviceToDevice);
    cudaMemcpyToSymbolAsync(cbf,  d_in[10], 1*sizeof(float),     0, cudaMemcpyDeviceToDevice);

    setup_pairs_kernel<<<(NPP + 255)/256, 256>>>();
    afm_kernel<<<BSZ, NTHREADS>>>(x, Emb, out);
}

// round 9
// speedup vs baseline: 1.0896x; 1.0544x over previous
#include <cuda_runtime.h>
#include <cstdint>

#define TT 100
#define DD 32
#define AA 16
#define NPAIR 4950
#define NTASK 156
#define NPP (NTASK*32)      // 4992, padded pair space
#define TTP 100
#define NTHREADS 128
#define NW (NTHREADS/32)
#define BSZ 1024

typedef unsigned long long ull;

// pair index table: (i<<8)|j for itertools.combinations order; dummies = (0,1)
__device__ __align__(16) int g_pairIJ[NPP];

// small weights in constant memory
__constant__ __align__(16) float cb[AA];
__constant__ __align__(16) float ch[AA];
__constant__ float cW1[DD*16];
__constant__ float cb1[16];
__constant__ float cW2m[16*8];
__constant__ float cb2[8];
__constant__ float cWf[8];
__constant__ float cbf[1];

__global__ void setup_pairs_kernel() {
    int p = blockIdx.x * blockDim.x + threadIdx.x;
    if (p >= NPP) return;
    if (p >= NPAIR) { g_pairIJ[p] = 1; return; }   // dummy pair (0,1)
    float disc = (float)((2*TT-1)*(2*TT-1) - 8*p);
    int i = (int)(((float)(2*TT-1) - sqrtf(disc)) * 0.5f);
    if (i < 0) i = 0;
    if (i > TT-2) i = TT-2;
    while (i > 0    && (i*(2*TT-1-i))/2 > p) i--;
    while (i < TT-2 && ((i+1)*(2*TT-1-(i+1)))/2 <= p) i++;
    int off = (i*(2*TT-1-i))/2;
    int j = p - off + i + 1;
    g_pairIJ[p] = (i << 8) | j;
}

__device__ __forceinline__ void mma_tf32(
    float& c0, float& c1, float& c2, float& c3,
    unsigned a0, unsigned a1, unsigned a2, unsigned a3,
    unsigned b0, unsigned b1)
{
    asm volatile(
        "mma.sync.aligned.m16n8k8.row.col.f32.tf32.tf32.f32 "
        "{%0,%1,%2,%3}, {%4,%5,%6,%7}, {%8,%9}, {%0,%1,%2,%3};"
        : "+f"(c0), "+f"(c1), "+f"(c2), "+f"(c3)
        : "r"(a0), "r"(a1), "r"(a2), "r"(a3), "r"(b0), "r"(b1));
}

__global__ __launch_bounds__(NTHREADS, 6) void afm_kernel(
    const int*   __restrict__ x,
    const float* __restrict__ Emb,
    const float* __restrict__ Wg,     // [32][16] row-major
    float* __restrict__ out)
{
    __shared__ __align__(16) float2 esT2[AA][TTP];  // [k2][t]: phys dims (2k2, 2k2+1)
    __shared__ __align__(16) float att[NPP];        // exp(logit), 0 on dummies
    __shared__ int   xs[TT];
    __shared__ float red[NW];
    __shared__ float poolv[DD];
    __shared__ float o1s[16];
    __shared__ float o2s[8];
    __shared__ float sm_isum;

    const int tid  = threadIdx.x;
    const int bidx = blockIdx.x;
    const int lane = tid & 31;
    const int wid  = tid >> 5;
    const int tig  = lane & 3;    // thread-in-group
    const int gid  = lane >> 2;   // group id (0..7)

    // ---- stage x indices, gather embeddings transposed: esT2[d2][t] ----
    if (tid < TT) xs[tid] = x[bidx*TT + tid];
    __syncthreads();
    for (int idx = tid; idx < TT*AA; idx += NTHREADS) {
        int t = idx >> 4, d2 = idx & 15;
        float2 v = ((const float2*)Emb)[(size_t)xs[t] * AA + d2];
        esT2[d2][t] = v;
    }

    // ---- per-lane W fragments (once). K-permutation: fragment col c in
    // {tig, tig+4} of k-block kb maps to PHYSICAL k = kb*8 + 2*tig + (c>=4).
    // B fragment (col-major k8 x n8): b0 row=tig, col=gid; b1 row=tig+4.
    unsigned wf[4][2][2];
    #pragma unroll
    for (int kb = 0; kb < 4; kb++)
        #pragma unroll
        for (int nb = 0; nb < 2; nb++) {
            wf[kb][nb][0] = __float_as_uint(Wg[(kb*8 + 2*tig    )*16 + nb*8 + gid]);
            wf[kb][nb][1] = __float_as_uint(Wg[(kb*8 + 2*tig + 1)*16 + nb*8 + gid]);
        }
    // C-fragment bias (cols nb*8 + 2*tig, +1) and h values for the epilogue
    float bb0[2], bb1[2], hh0[2], hh1[2];
    #pragma unroll
    for (int nb = 0; nb < 2; nb++) {
        bb0[nb] = cb[nb*8 + 2*tig];
        bb1[nb] = cb[nb*8 + 2*tig + 1];
        hh0[nb] = ch[nb*8 + 2*tig];
        hh1[nb] = ch[nb*8 + 2*tig + 1];
    }
    __syncthreads();

    // ================= PASS 1: tf32 MMA over pair chunks =================
    // chunk = 32 consecutive pairs; A = hb[32 pairs][32 k], z = A @ W
    float lsum = 0.f;
    for (int t0 = wid; t0 < NTASK; t0 += NW) {
        const int p0 = t0*32;
        // this lane's pair rows: gid + 8*s, s = 0..3
        int i_[4], j_[4];
        #pragma unroll
        for (int s = 0; s < 4; s++) {
            int v = g_pairIJ[p0 + gid + 8*s];
            i_[s] = v >> 8; j_[s] = v & 255;
        }
        // accumulators init to bias
        float c[2][2][4];
        #pragma unroll
        for (int mb = 0; mb < 2; mb++)
            #pragma unroll
            for (int nb = 0; nb < 2; nb++) {
                c[mb][nb][0] = bb0[nb]; c[mb][nb][1] = bb1[nb];
                c[mb][nb][2] = bb0[nb]; c[mb][nb][3] = bb1[nb];
            }

        #pragma unroll
        for (int kb = 0; kb < 4; kb++) {
            const int k2 = kb*4 + tig;   // physical dim pair (2k2, 2k2+1)
            #pragma unroll
            for (int mb = 0; mb < 2; mb++) {
                // rows rA = mb*16+gid (s=2mb), rB = rA+8 (s=2mb+1)
                ull eiA = *(const ull*)&esT2[k2][ i_[2*mb]   ];
                ull ejA = *(const ull*)&esT2[k2][ j_[2*mb]   ];
                ull eiB = *(const ull*)&esT2[k2][ i_[2*mb+1] ];
                ull ejB = *(const ull*)&esT2[k2][ j_[2*mb+1] ];
                ull prodA, prodB;
                asm("mul.rn.f32x2 %0, %1, %2;" : "=l"(prodA) : "l"(eiA), "l"(ejA));
                asm("mul.rn.f32x2 %0, %1, %2;" : "=l"(prodB) : "l"(eiB), "l"(ejB));
                unsigned a0, a1, a2, a3;
                asm("mov.b64 {%0,%1}, %2;" : "=r"(a0), "=r"(a2) : "l"(prodA));
                asm("mov.b64 {%0,%1}, %2;" : "=r"(a1), "=r"(a3) : "l"(prodB));
                #pragma unroll
                for (int nb = 0; nb < 2; nb++)
                    mma_tf32(c[mb][nb][0], c[mb][nb][1], c[mb][nb][2], c[mb][nb][3],
                             a0, a1, a2, a3, wf[kb][nb][0], wf[kb][nb][1]);
            }
        }

        // epilogue: relu + dot(h) per pair row; C row map: c0/c1 -> gid, c2/c3 -> gid+8
        float lg[4];
        #pragma unroll
        for (int mb = 0; mb < 2; mb++) {
            float a = 0.f, bqq = 0.f;
            #pragma unroll
            for (int nb = 0; nb < 2; nb++) {
                a   = fmaf(fmaxf(c[mb][nb][0], 0.f), hh0[nb], a);
                a   = fmaf(fmaxf(c[mb][nb][1], 0.f), hh1[nb], a);
                bqq = fmaf(fmaxf(c[mb][nb][2], 0.f), hh0[nb], bqq);
                bqq = fmaf(fmaxf(c[mb][nb][3], 0.f), hh1[nb], bqq);
            }
            lg[2*mb]   = a;     // row mb*16 + gid
            lg[2*mb+1] = bqq;   // row mb*16 + gid + 8
        }
        // reduce over the 4-lane quad (partial over A-dims)
        #pragma unroll
        for (int s = 0; s < 4; s++) {
            lg[s] += __shfl_xor_sync(0xffffffffu, lg[s], 1);
            lg[s] += __shfl_xor_sync(0xffffffffu, lg[s], 2);
        }
        // lane (tig,gid) owns pair row 8*tig + gid
        float myl = (tig == 0) ? lg[0] : (tig == 1) ? lg[1] : (tig == 2) ? lg[2] : lg[3];
        int p = p0 + 8*tig + gid;
        float E = (p < NPAIR) ? __expf(myl) : 0.f;
        att[p] = E;
        lsum += E;
    }

    // ---- block reduce lsum -> 1/sum ----
    #pragma unroll
    for (int o = 16; o > 0; o >>= 1) lsum += __shfl_xor_sync(0xffffffffu, lsum, o);
    if (lane == 0) red[wid] = lsum;
    __syncthreads();
    if (tid == 0) {
        float s = 0.f;
        #pragma unroll
        for (int w = 0; w < NW; w++) s += red[w];
        sm_isum = 1.f / s;
    }
    __syncthreads();
    const float inv = sm_isum;

    // ================= PASS 2: attention-pooled sum =================
    // warp owns 4 float2-dims (d2 = wid*4+q); lanes stream 32 consecutive pairs
    {
        ull acc[4];
        #pragma unroll
        for (int q = 0; q < 4; q++) acc[q] = 0ull;
        const int d2base = wid * 4;

        for (int p0 = 0; p0 < NPP; p0 += 32) {
            int v = g_pairIJ[p0 + lane];
            float a = att[p0 + lane];          // coalesced LDS; 0 on dummies
            int i = v >> 8, j = v & 255;
            ull aa;
            asm("mov.b64 %0, {%1, %1};" : "=l"(aa) : "f"(a));
            #pragma unroll
            for (int q = 0; q < 4; q++) {
                ull vi = *(const ull*)&esT2[d2base + q][i];
                ull vj = *(const ull*)&esT2[d2base + q][j];
                ull prod;
                asm("mul.rn.f32x2 %0, %1, %2;" : "=l"(prod) : "l"(vi), "l"(vj));
                asm("fma.rn.f32x2 %0, %1, %2, %0;" : "+l"(acc[q]) : "l"(aa), "l"(prod));
            }
        }
        #pragma unroll
        for (int q = 0; q < 4; q++) {
            float lo, hi;
            asm("mov.b64 {%0, %1}, %2;" : "=f"(lo), "=f"(hi) : "l"(acc[q]));
            #pragma unroll
            for (int o = 16; o > 0; o >>= 1) {
                lo += __shfl_xor_sync(0xffffffffu, lo, o);
                hi += __shfl_xor_sync(0xffffffffu, hi, o);
            }
            if (lane == 0) {
                poolv[2*(d2base+q)]   = lo * inv;
                poolv[2*(d2base+q)+1] = hi * inv;
            }
        }
    }
    __syncthreads();

    // ================= tiny MLP (weights from constant) =================
    if (tid < 16) {
        float z = cb1[tid];
        #pragma unroll
        for (int d = 0; d < DD; d++) z = fmaf(poolv[d], cW1[d*16 + tid], z);
        o1s[tid] = fmaxf(z, 0.f);
    }
    __syncthreads();
    if (tid < 8) {
        float z = cb2[tid];
        #pragma unroll
        for (int c = 0; c < 16; c++) z = fmaf(o1s[c], cW2m[c*8 + tid], z);
        o2s[tid] = fmaxf(z, 0.f);
    }
    __syncthreads();
    if (tid == 0) {
        float z = cbf[0];
        #pragma unroll
        for (int c = 0; c < 8; c++) z = fmaf(o2s[c], cWf[c], z);
        out[bidx] = 1.f / (1.f + __expf(-z));
    }
}

extern "C" void kernel_launch(void* const* d_in, const int* in_sizes, int n_in,
                              void* d_out, int out_size) {
    const int*   x   = (const int*)  d_in[0];
    const float* Emb = (const float*)d_in[1];
    const float* Wg  = (const float*)d_in[2];
    float* out = (float*)d_out;

    cudaMemcpyToSymbolAsync(cb,   d_in[3],  AA*sizeof(float),    0, cudaMemcpyDeviceToDevice);
    cudaMemcpyToSymbolAsync(ch,   d_in[4],  AA*sizeof(float),    0, cudaMemcpyDeviceToDevice);
    cudaMemcpyToSymbolAsync(cW1,  d_in[5],  DD*16*sizeof(float), 0, cudaMemcpyDeviceToDevice);
    cudaMemcpyToSymbolAsync(cb1,  d_in[6],  16*sizeof(float),    0, cudaMemcpyDeviceToDevice);
    cudaMemcpyToSymbolAsync(cW2m, d_in[7],  16*8*sizeof(float),  0, cudaMemcpyDeviceToDevice);
    cudaMemcpyToSymbolAsync(cb2,  d_in[8],  8*sizeof(float),     0, cudaMemcpyDeviceToDevice);
    cudaMemcpyToSymbolAsync(cWf,  d_in[9],  8*sizeof(float),     0, cudaMemcpyDeviceToDevice);
    cudaMemcpyToSymbolAsync(cbf,  d_in[10], 1*sizeof(float),     0, cudaMemcpyDeviceToDevice);

    setup_pairs_kernel<<<(NPP + 255)/256, 256>>>();
    afm_kernel<<<BSZ, NTHREADS>>>(x, Emb, Wg, out);
}

// round 10
// speedup vs baseline: 1.3249x; 1.2160x over previous
#include <cuda_runtime.h>
#include <cstdint>

#define TT 100
#define DD 32
#define AA 16
#define NPAIR 4950
#define NTASK 156
#define NPP (NTASK*32)      // 4992, padded pair space
#define TTP 100
#define NTHREADS 128
#define NW (NTHREADS/32)
#define BSZ 1024

typedef unsigned long long ull;

// pair index table: (i<<8)|j for itertools.combinations order; dummies = (0,1)
__device__ __align__(16) int g_pairIJ[NPP];

// small weights in constant memory
__constant__ __align__(16) float cb[AA];
__constant__ __align__(16) float ch[AA];
__constant__ float cW1[DD*16];
__constant__ float cb1[16];
__constant__ float cW2m[16*8];
__constant__ float cb2[8];
__constant__ float cWf[8];
__constant__ float cbf[1];

__global__ void setup_pairs_kernel() {
    int p = blockIdx.x * blockDim.x + threadIdx.x;
    if (p >= NPP) return;
    if (p >= NPAIR) { g_pairIJ[p] = 1; return; }   // dummy pair (0,1)
    float disc = (float)((2*TT-1)*(2*TT-1) - 8*p);
    int i = (int)(((float)(2*TT-1) - sqrtf(disc)) * 0.5f);
    if (i < 0) i = 0;
    if (i > TT-2) i = TT-2;
    while (i > 0    && (i*(2*TT-1-i))/2 > p) i--;
    while (i < TT-2 && ((i+1)*(2*TT-1-(i+1)))/2 <= p) i++;
    int off = (i*(2*TT-1-i))/2;
    int j = p - off + i + 1;
    g_pairIJ[p] = (i << 8) | j;
}

__device__ __forceinline__ void mma_tf32(
    float& c0, float& c1, float& c2, float& c3,
    unsigned a0, unsigned a1, unsigned a2, unsigned a3,
    unsigned b0, unsigned b1)
{
    asm volatile(
        "mma.sync.aligned.m16n8k8.row.col.f32.tf32.tf32.f32 "
        "{%0,%1,%2,%3}, {%4,%5,%6,%7}, {%8,%9}, {%0,%1,%2,%3};"
        : "+f"(c0), "+f"(c1), "+f"(c2), "+f"(c3)
        : "r"(a0), "r"(a1), "r"(a2), "r"(a3), "r"(b0), "r"(b1));
}

__global__ __launch_bounds__(NTHREADS, 5) void afm_kernel(
    const int*   __restrict__ x,
    const float* __restrict__ Emb,
    const float* __restrict__ Wg,     // [32][16] row-major
    float* __restrict__ out)
{
    __shared__ __align__(16) float2 esT2[AA][TTP];  // [k2][t]: phys dims (2k2, 2k2+1)
    __shared__ int   xs[TT];
    __shared__ float red[NW];
    __shared__ float poolw[NW][DD];   // per-warp pooled partials
    __shared__ float poolv[DD];
    __shared__ float o1s[16];
    __shared__ float o2s[8];
    __shared__ float sm_isum;

    const int tid  = threadIdx.x;
    const int bidx = blockIdx.x;
    const int lane = tid & 31;
    const int wid  = tid >> 5;
    const int tig  = lane & 3;    // thread-in-group
    const int gid  = lane >> 2;   // group id (0..7)

    // ---- stage x indices, gather embeddings transposed: esT2[d2][t] ----
    if (tid < TT) xs[tid] = x[bidx*TT + tid];
    __syncthreads();
    for (int idx = tid; idx < TT*AA; idx += NTHREADS) {
        int t = idx >> 4, d2 = idx & 15;
        float2 v = ((const float2*)Emb)[(size_t)xs[t] * AA + d2];
        esT2[d2][t] = v;
    }

    // ---- per-lane W fragments. K-permutation: fragment col c in {tig, tig+4}
    // of k-block kb maps to PHYSICAL k = kb*8 + 2*tig + (c>=4).
    unsigned wf[4][2][2];
    #pragma unroll
    for (int kb = 0; kb < 4; kb++)
        #pragma unroll
        for (int nb = 0; nb < 2; nb++) {
            wf[kb][nb][0] = __float_as_uint(Wg[(kb*8 + 2*tig    )*16 + nb*8 + gid]);
            wf[kb][nb][1] = __float_as_uint(Wg[(kb*8 + 2*tig + 1)*16 + nb*8 + gid]);
        }
    float bb0[2], bb1[2], hh0[2], hh1[2];
    #pragma unroll
    for (int nb = 0; nb < 2; nb++) {
        bb0[nb] = cb[nb*8 + 2*tig];
        bb1[nb] = cb[nb*8 + 2*tig + 1];
        hh0[nb] = ch[nb*8 + 2*tig];
        hh1[nb] = ch[nb*8 + 2*tig + 1];
    }
    __syncthreads();

    // ============ SINGLE FUSED PASS: MMA logits -> E -> pooled ============
    // chunk = 32 consecutive pairs; pooled accumulates unnormalized E*prod.
    // acc[kb] covers dims (2k2, 2k2+1), k2 = kb*4 + tig.
    float lsum = 0.f;
    ull acc[4];
    #pragma unroll
    for (int kb = 0; kb < 4; kb++) acc[kb] = 0ull;

    for (int t0 = wid; t0 < NTASK; t0 += NW) {
        const int p0 = t0*32;
        // this lane's pair rows: gid + 8*s, s = 0..3
        int i_[4], j_[4];
        #pragma unroll
        for (int s = 0; s < 4; s++) {
            int v = g_pairIJ[p0 + gid + 8*s];
            i_[s] = v >> 8; j_[s] = v & 255;
        }
        float c[2][2][4];
        #pragma unroll
        for (int mb = 0; mb < 2; mb++)
            #pragma unroll
            for (int nb = 0; nb < 2; nb++) {
                c[mb][nb][0] = bb0[nb]; c[mb][nb][1] = bb1[nb];
                c[mb][nb][2] = bb0[nb]; c[mb][nb][3] = bb1[nb];
            }

        ull prod[4][4];   // [kb][s]: product f32x2 for pair row gid+8s, dims k2=kb*4+tig
        #pragma unroll
        for (int kb = 0; kb < 4; kb++) {
            const int k2 = kb*4 + tig;
            #pragma unroll
            for (int mb = 0; mb < 2; mb++) {
                ull eiA = *(const ull*)&esT2[k2][ i_[2*mb]   ];
                ull ejA = *(const ull*)&esT2[k2][ j_[2*mb]   ];
                ull eiB = *(const ull*)&esT2[k2][ i_[2*mb+1] ];
                ull ejB = *(const ull*)&esT2[k2][ j_[2*mb+1] ];
                ull prodA, prodB;
                asm("mul.rn.f32x2 %0, %1, %2;" : "=l"(prodA) : "l"(eiA), "l"(ejA));
                asm("mul.rn.f32x2 %0, %1, %2;" : "=l"(prodB) : "l"(eiB), "l"(ejB));
                prod[kb][2*mb]   = prodA;
                prod[kb][2*mb+1] = prodB;
                unsigned a0, a1, a2, a3;
                asm("mov.b64 {%0,%1}, %2;" : "=r"(a0), "=r"(a2) : "l"(prodA));
                asm("mov.b64 {%0,%1}, %2;" : "=r"(a1), "=r"(a3) : "l"(prodB));
                #pragma unroll
                for (int nb = 0; nb < 2; nb++)
                    mma_tf32(c[mb][nb][0], c[mb][nb][1], c[mb][nb][2], c[mb][nb][3],
                             a0, a1, a2, a3, wf[kb][nb][0], wf[kb][nb][1]);
            }
        }

        // epilogue: relu + dot(h); C row map: c0/c1 -> gid, c2/c3 -> gid+8
        float lg[4];
        #pragma unroll
        for (int mb = 0; mb < 2; mb++) {
            float a = 0.f, bqq = 0.f;
            #pragma unroll
            for (int nb = 0; nb < 2; nb++) {
                a   = fmaf(fmaxf(c[mb][nb][0], 0.f), hh0[nb], a);
                a   = fmaf(fmaxf(c[mb][nb][1], 0.f), hh1[nb], a);
                bqq = fmaf(fmaxf(c[mb][nb][2], 0.f), hh0[nb], bqq);
                bqq = fmaf(fmaxf(c[mb][nb][3], 0.f), hh1[nb], bqq);
            }
            lg[2*mb]   = a;
            lg[2*mb+1] = bqq;
        }
        #pragma unroll
        for (int s = 0; s < 4; s++) {
            lg[s] += __shfl_xor_sync(0xffffffffu, lg[s], 1);
            lg[s] += __shfl_xor_sync(0xffffffffu, lg[s], 2);
        }
        // lane (tig,gid) owns pair row 8*tig + gid
        float myl = (tig == 0) ? lg[0] : (tig == 1) ? lg[1] : (tig == 2) ? lg[2] : lg[3];
        int p = p0 + 8*tig + gid;
        float E = (p < NPAIR) ? __expf(myl) : 0.f;
        lsum += E;

        // E for my pair rows gid+8s lives on lane 4*gid + s (same quad)
        #pragma unroll
        for (int s = 0; s < 4; s++) {
            float Es = __shfl_sync(0xffffffffu, E, 4*gid + s);
            ull ppE;
            asm("mov.b64 %0, {%1, %1};" : "=l"(ppE) : "f"(Es));
            #pragma unroll
            for (int kb = 0; kb < 4; kb++)
                asm("fma.rn.f32x2 %0, %1, %2, %0;"
                    : "+l"(acc[kb]) : "l"(ppE), "l"(prod[kb][s]));
        }
    }

    // ---- reduce pooled partials over gid (lane = 4*gid + tig) ----
    #pragma unroll
    for (int kb = 0; kb < 4; kb++) {
        float lo, hi;
        asm("mov.b64 {%0, %1}, %2;" : "=f"(lo), "=f"(hi) : "l"(acc[kb]));
        #pragma unroll
        for (int o = 4; o < 32; o <<= 1) {
            lo += __shfl_xor_sync(0xffffffffu, lo, o);
            hi += __shfl_xor_sync(0xffffffffu, hi, o);
        }
        if (gid == 0) {
            int d2 = kb*4 + tig;
            poolw[wid][2*d2]   = lo;
            poolw[wid][2*d2+1] = hi;
        }
    }

    // ---- block reduce lsum -> 1/sum ----
    #pragma unroll
    for (int o = 16; o > 0; o >>= 1) lsum += __shfl_xor_sync(0xffffffffu, lsum, o);
    if (lane == 0) red[wid] = lsum;
    __syncthreads();
    if (tid == 0) {
        float s = 0.f;
        #pragma unroll
        for (int w = 0; w < NW; w++) s += red[w];
        sm_isum = 1.f / s;
    }
    __syncthreads();
    const float inv = sm_isum;

    // ---- combine per-warp pooled partials, normalize ----
    if (tid < DD) {
        float s = 0.f;
        #pragma unroll
        for (int w = 0; w < NW; w++) s += poolw[w][tid];
        poolv[tid] = s * inv;
    }
    __syncthreads();

    // ================= tiny MLP (weights from constant) =================
    if (tid < 16) {
        float z = cb1[tid];
        #pragma unroll
        for (int d = 0; d < DD; d++) z = fmaf(poolv[d], cW1[d*16 + tid], z);
        o1s[tid] = fmaxf(z, 0.f);
    }
    __syncthreads();
    if (tid < 8) {
        float z = cb2[tid];
        #pragma unroll
        for (int c2 = 0; c2 < 16; c2++) z = fmaf(o1s[c2], cW2m[c2*8 + tid], z);
        o2s[tid] = fmaxf(z, 0.f);
    }
    __syncthreads();
    if (tid == 0) {
        float z = cbf[0];
        #pragma unroll
        for (int c2 = 0; c2 < 8; c2++) z = fmaf(o2s[c2], cWf[c2], z);
        out[bidx] = 1.f / (1.f + __expf(-z));
    }
}

extern "C" void kernel_launch(void* const* d_in, const int* in_sizes, int n_in,
                              void* d_out, int out_size) {
    const int*   x   = (const int*)  d_in[0];
    const float* Emb = (const float*)d_in[1];
    const float* Wg  = (const float*)d_in[2];
    float* out = (float*)d_out;

    cudaMemcpyToSymbolAsync(cb,   d_in[3],  AA*sizeof(float),    0, cudaMemcpyDeviceToDevice);
    cudaMemcpyToSymbolAsync(ch,   d_in[4],  AA*sizeof(float),    0, cudaMemcpyDeviceToDevice);
    cudaMemcpyToSymbolAsync(cW1,  d_in[5],  DD*16*sizeof(float), 0, cudaMemcpyDeviceToDevice);
    cudaMemcpyToSymbolAsync(cb1,  d_in[6],  16*sizeof(float),    0, cudaMemcpyDeviceToDevice);
    cudaMemcpyToSymbolAsync(cW2m, d_in[7],  16*8*sizeof(float),  0, cudaMemcpyDeviceToDevice);
    cudaMemcpyToSymbolAsync(cb2,  d_in[8],  8*sizeof(float),     0, cudaMemcpyDeviceToDevice);
    cudaMemcpyToSymbolAsync(cWf,  d_in[9],  8*sizeof(float),     0, cudaMemcpyDeviceToDevice);
    cudaMemcpyToSymbolAsync(cbf,  d_in[10], 1*sizeof(float),     0, cudaMemcpyDeviceToDevice);

    setup_pairs_kernel<<<(NPP + 255)/256, 256>>>();
    afm_kernel<<<BSZ, NTHREADS>>>(x, Emb, Wg, out);
}